// round 3
// baseline (speedup 1.0000x reference)
#include <cuda_runtime.h>
#include <math.h>

// Problem constants
#define HSZ    2048
#define SEQ    2048
#define NBATCH 2
#define NHEADS 16
#define HDIM   128
#define NTOK   (NBATCH * SEQ)     // 4096 tokens
#define KQKV   (3 * HSZ)          // 6144

// Scratch (device globals; no allocation allowed)
__device__ float g_qkv[(size_t)NTOK * KQKV];   // [4096, 6144] : q | k | v
__device__ float g_ctx[(size_t)NTOK * HSZ];    // [4096, 2048]

// ---------------------------------------------------------------------------
// Classic 128x128x16 fp32 SGEMM with bias: C[M,N] = A[M,K] @ B[K,N] + bias[N]
// 256 threads, 8x8 per-thread tile, float4 everywhere.
// ---------------------------------------------------------------------------
#define GBM 128
#define GBN 128
#define GBK 16

__global__ __launch_bounds__(256, 2)
void sgemm_bias_kernel(const float* __restrict__ A, const float* __restrict__ B,
                       const float* __restrict__ bias, float* __restrict__ C,
                       int M, int N, int K)
{
    __shared__ float As[GBK][GBM + 4];   // k-major A tile (transposed on load)
    __shared__ float Bs[GBK][GBN + 4];

    const int tid = threadIdx.x;
    const int tr  = tid >> 4;            // 0..15 -> rows tr*8..tr*8+7
    const int tc  = tid & 15;            // 0..15 -> cols tc*8..tc*8+7
    const int m0  = blockIdx.y * GBM;
    const int n0  = blockIdx.x * GBN;

    float acc[8][8];
#pragma unroll
    for (int i = 0; i < 8; i++)
#pragma unroll
        for (int j = 0; j < 8; j++) acc[i][j] = 0.f;

    const float* Ab = A + (size_t)m0 * K;
    const float* Bb = B + n0;

    for (int kt = 0; kt < K; kt += GBK) {
        // A tile: 128 rows x 16 k -> 512 float4, 2 per thread, store transposed
#pragma unroll
        for (int i = 0; i < 2; i++) {
            int f   = tid + i * 256;
            int row = f >> 2;            // 0..127
            int c4  = (f & 3) << 2;      // 0,4,8,12
            float4 v = *(const float4*)(Ab + (size_t)row * K + kt + c4);
            As[c4 + 0][row] = v.x;
            As[c4 + 1][row] = v.y;
            As[c4 + 2][row] = v.z;
            As[c4 + 3][row] = v.w;
        }
        // B tile: 16 k x 128 cols -> direct float4 copy
#pragma unroll
        for (int i = 0; i < 2; i++) {
            int f   = tid + i * 256;
            int row = f >> 5;            // 0..15
            int c4  = (f & 31) << 2;     // 0..124
            *(float4*)&Bs[row][c4] =
                *(const float4*)(Bb + (size_t)(kt + row) * N + c4);
        }
        __syncthreads();

#pragma unroll
        for (int k = 0; k < GBK; k++) {
            float a[8], b[8];
            *(float4*)&a[0] = *(const float4*)&As[k][tr * 8];
            *(float4*)&a[4] = *(const float4*)&As[k][tr * 8 + 4];
            *(float4*)&b[0] = *(const float4*)&Bs[k][tc * 8];
            *(float4*)&b[4] = *(const float4*)&Bs[k][tc * 8 + 4];
#pragma unroll
            for (int i = 0; i < 8; i++)
#pragma unroll
                for (int j = 0; j < 8; j++)
                    acc[i][j] += a[i] * b[j];
        }
        __syncthreads();
    }

    // Epilogue: add bias, vectorized store
#pragma unroll
    for (int i = 0; i < 8; i++) {
        int row = m0 + tr * 8 + i;
        float* Cr = C + (size_t)row * N + n0 + tc * 8;
        const float* br = bias + n0 + tc * 8;
#pragma unroll
        for (int j = 0; j < 8; j += 4) {
            float4 v;
            v.x = acc[i][j + 0] + br[j + 0];
            v.y = acc[i][j + 1] + br[j + 1];
            v.z = acc[i][j + 2] + br[j + 2];
            v.w = acc[i][j + 3] + br[j + 3];
            *(float4*)(Cr + j) = v;
        }
    }
}

// ---------------------------------------------------------------------------
// Causal flash attention, fp32. Br=Bc=64, d=128. 256 threads.
// Equivalent to reference (its mask/max/rescale path reduces to plain causal
// softmax with scale 1/sqrt(128); the -65504 fills underflow exp() to 0).
// Grid: (SEQ/64, NBATCH*NHEADS). blockIdx.x reversed so heavy diagonal
// blocks launch first.
// ---------------------------------------------------------------------------
#define QP 68      // padded inner dim for 64-wide tiles (k-major Q/K, Ps rows)
#define VP 132     // padded row for V (128 + 4)
#define BIG_NEG (-1e30f)

__global__ __launch_bounds__(256, 1)
void flash_attn_kernel()
{
    extern __shared__ float sm[];
    float* Qs = sm;                      // [128][QP] k-major: Qs[k*QP + r]
    float* Ks = Qs + 128 * QP;           // [128][QP] k-major: Ks[k*QP + c]
    float* Vs = Ks + 128 * QP;           // [64][VP]  row-major: Vs[c*VP + d]
    float* Ps = Vs + 64 * VP;            // [64][QP]  row-major: Ps[r*QP + c]

    const int tid = threadIdx.x;
    const int tr  = tid >> 4;            // 0..15 -> q rows tr*4..tr*4+3
    const int tc  = tid & 15;            // 0..15 -> key cols tc*4.. / out cols tc*8..

    const int qt   = (SEQ / 64 - 1) - blockIdx.x;   // heavy tiles first
    const int bh   = blockIdx.y;
    const int b    = bh >> 4;
    const int head = bh & 15;
    const int q0   = qt * 64;

    const float* base = g_qkv + (size_t)b * SEQ * KQKV + head * HDIM;

    // Load Q tile (64 x 128) transposed into k-major smem
#pragma unroll
    for (int i = 0; i < 8; i++) {
        int f  = tid + i * 256;
        int r  = f >> 5;                 // 0..63
        int d4 = (f & 31) << 2;          // 0..124
        float4 v = *(const float4*)(base + (size_t)(q0 + r) * KQKV + d4);
        Qs[(d4 + 0) * QP + r] = v.x;
        Qs[(d4 + 1) * QP + r] = v.y;
        Qs[(d4 + 2) * QP + r] = v.z;
        Qs[(d4 + 3) * QP + r] = v.w;
    }

    float o[4][8];
#pragma unroll
    for (int i = 0; i < 4; i++)
#pragma unroll
        for (int j = 0; j < 8; j++) o[i][j] = 0.f;
    float mrow[4] = {BIG_NEG, BIG_NEG, BIG_NEG, BIG_NEG};
    float lrow[4] = {0.f, 0.f, 0.f, 0.f};

    const float scale = 0.088388347648318447f;   // 1/sqrt(128)

    for (int kt = 0; kt <= qt; kt++) {
        const int j0 = kt * 64;
        __syncthreads();   // previous tile fully consumed (also covers Q load)

        // Load K,V tiles (K transposed to k-major, V row-major)
#pragma unroll
        for (int i = 0; i < 8; i++) {
            int f  = tid + i * 256;
            int c  = f >> 5;
            int d4 = (f & 31) << 2;
            const float* kr = base + (size_t)(j0 + c) * KQKV + HSZ + d4;
            float4 kv = *(const float4*)kr;
            Ks[(d4 + 0) * QP + c] = kv.x;
            Ks[(d4 + 1) * QP + c] = kv.y;
            Ks[(d4 + 2) * QP + c] = kv.z;
            Ks[(d4 + 3) * QP + c] = kv.w;
            *(float4*)&Vs[c * VP + d4] = *(const float4*)(kr + HSZ);
        }
        __syncthreads();

        // S = Q @ K^T  (64x64 tile; this thread: 4x4 at rows tr*4, cols tc*4)
        float s[4][4];
#pragma unroll
        for (int i = 0; i < 4; i++)
#pragma unroll
            for (int j = 0; j < 4; j++) s[i][j] = 0.f;

#pragma unroll 8
        for (int k = 0; k < 128; k++) {
            float a[4], c[4];
            *(float4*)a = *(const float4*)&Qs[k * QP + tr * 4];
            *(float4*)c = *(const float4*)&Ks[k * QP + tc * 4];
#pragma unroll
            for (int i = 0; i < 4; i++)
#pragma unroll
                for (int j = 0; j < 4; j++)
                    s[i][j] += a[i] * c[j];
        }

#pragma unroll
        for (int i = 0; i < 4; i++)
#pragma unroll
            for (int j = 0; j < 4; j++) s[i][j] *= scale;

        if (kt == qt) {   // diagonal tile: causal mask (j0 == q0 here)
#pragma unroll
            for (int i = 0; i < 4; i++)
#pragma unroll
                for (int j = 0; j < 4; j++)
                    if (tc * 4 + j > tr * 4 + i) s[i][j] = BIG_NEG;
        }

        // Online softmax per row; reductions within the 16-lane tc group
#pragma unroll
        for (int i = 0; i < 4; i++) {
            float tm = fmaxf(fmaxf(s[i][0], s[i][1]), fmaxf(s[i][2], s[i][3]));
            tm = fmaxf(tm, __shfl_xor_sync(0xffffffffu, tm, 1));
            tm = fmaxf(tm, __shfl_xor_sync(0xffffffffu, tm, 2));
            tm = fmaxf(tm, __shfl_xor_sync(0xffffffffu, tm, 4));
            tm = fmaxf(tm, __shfl_xor_sync(0xffffffffu, tm, 8));
            float mn = fmaxf(mrow[i], tm);

            float p[4];
            float rs = 0.f;
#pragma unroll
            for (int j = 0; j < 4; j++) {
                p[j] = __expf(s[i][j] - mn);
                rs += p[j];
            }
            rs += __shfl_xor_sync(0xffffffffu, rs, 1);
            rs += __shfl_xor_sync(0xffffffffu, rs, 2);
            rs += __shfl_xor_sync(0xffffffffu, rs, 4);
            rs += __shfl_xor_sync(0xffffffffu, rs, 8);

            float corr = __expf(mrow[i] - mn);
            lrow[i] = lrow[i] * corr + rs;
            mrow[i] = mn;
#pragma unroll
            for (int n = 0; n < 8; n++) o[i][n] *= corr;

            *(float4*)&Ps[(tr * 4 + i) * QP + tc * 4] =
                make_float4(p[0], p[1], p[2], p[3]);
        }
        __syncthreads();

        // O += P @ V   (this thread: rows tr*4..+3, cols tc*8..+7)
#pragma unroll 2
        for (int j = 0; j < 64; j += 4) {
            float pa[4][4];
#pragma unroll
            for (int i = 0; i < 4; i++)
                *(float4*)pa[i] = *(const float4*)&Ps[(tr * 4 + i) * QP + j];
#pragma unroll
            for (int jj = 0; jj < 4; jj++) {
                float4 v0 = *(const float4*)&Vs[(j + jj) * VP + tc * 8];
                float4 v1 = *(const float4*)&Vs[(j + jj) * VP + tc * 8 + 4];
#pragma unroll
                for (int i = 0; i < 4; i++) {
                    o[i][0] += pa[i][jj] * v0.x;
                    o[i][1] += pa[i][jj] * v0.y;
                    o[i][2] += pa[i][jj] * v0.z;
                    o[i][3] += pa[i][jj] * v0.w;
                    o[i][4] += pa[i][jj] * v1.x;
                    o[i][5] += pa[i][jj] * v1.y;
                    o[i][6] += pa[i][jj] * v1.z;
                    o[i][7] += pa[i][jj] * v1.w;
                }
            }
        }
    }

    // Epilogue: normalize and write ctx[b, q0+r, head*128 + n]
    float* cbase = g_ctx + (size_t)(b * SEQ + q0) * HSZ + head * HDIM;
#pragma unroll
    for (int i = 0; i < 4; i++) {
        float inv = 1.f / lrow[i];
        float* dst = cbase + (size_t)(tr * 4 + i) * HSZ + tc * 8;
        float4 w0, w1;
        w0.x = o[i][0] * inv; w0.y = o[i][1] * inv;
        w0.z = o[i][2] * inv; w0.w = o[i][3] * inv;
        w1.x = o[i][4] * inv; w1.y = o[i][5] * inv;
        w1.z = o[i][6] * inv; w1.w = o[i][7] * inv;
        *(float4*)(dst)     = w0;
        *(float4*)(dst + 4) = w1;
    }
}

// ---------------------------------------------------------------------------
extern "C" void kernel_launch(void* const* d_in, const int* in_sizes, int n_in,
                              void* d_out, int out_size)
{
    const float* hs   = (const float*)d_in[0];  // hidden_states [2,2048,2048]
    // d_in[1] = ltor_mask (causal; hardcoded in the flash kernel)
    const float* Wqkv = (const float*)d_in[2];  // [2048, 6144]
    const float* bqkv = (const float*)d_in[3];  // [6144]
    const float* Wout = (const float*)d_in[4];  // [2048, 2048]
    const float* bout = (const float*)d_in[5];  // [2048]
    float* out = (float*)d_out;                 // [2,2048,2048] fp32

    float* qkv = nullptr;
    float* ctx = nullptr;
    cudaGetSymbolAddress((void**)&qkv, g_qkv);
    cudaGetSymbolAddress((void**)&ctx, g_ctx);

    dim3 blk(256);

    // 1) QKV projection: [4096,2048] @ [2048,6144] + b
    sgemm_bias_kernel<<<dim3(KQKV / GBN, NTOK / GBM), blk>>>(
        hs, Wqkv, bqkv, qkv, NTOK, KQKV, HSZ);

    // 2) Causal flash attention -> g_ctx
    size_t smem = (size_t)(2 * 128 * QP + 64 * VP + 64 * QP) * sizeof(float);
    cudaFuncSetAttribute(flash_attn_kernel,
                         cudaFuncAttributeMaxDynamicSharedMemorySize, (int)smem);
    flash_attn_kernel<<<dim3(SEQ / 64, NBATCH * NHEADS), blk, smem>>>();

    // 3) Output projection: [4096,2048] @ [2048,2048] + b
    sgemm_bias_kernel<<<dim3(HSZ / GBN, NTOK / GBM), blk>>>(
        ctx, Wout, bout, out, NTOK, HSZ, HSZ);
}

// round 5
// speedup vs baseline: 1.7931x; 1.7931x over previous
#include <cuda_runtime.h>
#include <cuda_bf16.h>
#include <math.h>
#include <stdint.h>

// Problem constants
#define HSZ    2048
#define SEQ    2048
#define NBATCH 2
#define NHEADS 16
#define HDIM   128
#define NTOK   (NBATCH * SEQ)     // 4096 tokens
#define KQKV   (3 * HSZ)          // 6144

// ---------------------------------------------------------------------------
// Scratch (device globals; no allocation allowed)
// ---------------------------------------------------------------------------
__device__ float g_qkv[(size_t)NTOK * KQKV];            // [4096, 6144] fp32
__device__ float g_ctx[(size_t)NTOK * HSZ];             // [4096, 2048] fp32
__device__ __nv_bfloat16 g_a_hi[(size_t)NTOK * HSZ];    // hs split
__device__ __nv_bfloat16 g_a_lo[(size_t)NTOK * HSZ];
__device__ __nv_bfloat16 g_c_hi[(size_t)NTOK * HSZ];    // ctx split
__device__ __nv_bfloat16 g_c_lo[(size_t)NTOK * HSZ];
__device__ __nv_bfloat16 g_wq_hi[(size_t)KQKV * HSZ];   // Wqkv^T [6144,2048]
__device__ __nv_bfloat16 g_wq_lo[(size_t)KQKV * HSZ];
__device__ __nv_bfloat16 g_wo_hi[(size_t)HSZ * HSZ];    // Wout^T [2048,2048]
__device__ __nv_bfloat16 g_wo_lo[(size_t)HSZ * HSZ];

// ---------------------------------------------------------------------------
// Helpers
// ---------------------------------------------------------------------------
__device__ __forceinline__ uint32_t smem_u32_of(const void* p) {
    uint32_t a;
    asm("{ .reg .u64 t; cvta.to.shared.u64 t, %1; cvt.u32.u64 %0, t; }"
        : "=r"(a) : "l"(p));
    return a;
}

#define CP_ASYNC16(dst, src) \
    asm volatile("cp.async.cg.shared.global [%0], [%1], 16;" \
                 :: "r"(dst), "l"(src) : "memory")
#define CP_COMMIT()  asm volatile("cp.async.commit_group;" ::: "memory")
#define CP_WAIT2()   asm volatile("cp.async.wait_group 2;" ::: "memory")

#define SWZ(o) ((o) ^ (((o) >> 3) & 0x70))

__device__ __forceinline__ void ldsm_x4(uint32_t* r, uint32_t addr) {
    asm volatile("ldmatrix.sync.aligned.m8n8.x4.shared.b16 {%0,%1,%2,%3}, [%4];"
                 : "=r"(r[0]), "=r"(r[1]), "=r"(r[2]), "=r"(r[3]) : "r"(addr));
}

__device__ __forceinline__ void mma_bf16(float* c, const uint32_t* a,
                                         const uint32_t* b) {
    asm volatile(
        "mma.sync.aligned.m16n8k16.row.col.f32.bf16.bf16.f32 "
        "{%0,%1,%2,%3}, {%4,%5,%6,%7}, {%8,%9}, {%0,%1,%2,%3};"
        : "+f"(c[0]), "+f"(c[1]), "+f"(c[2]), "+f"(c[3])
        : "r"(a[0]), "r"(a[1]), "r"(a[2]), "r"(a[3]), "r"(b[0]), "r"(b[1]));
}

// ---------------------------------------------------------------------------
// Prep kernels: fp32 -> bf16 hi/lo split (elementwise and transposed)
// ---------------------------------------------------------------------------
__global__ void split_kernel(const float* __restrict__ x,
                             __nv_bfloat16* __restrict__ H,
                             __nv_bfloat16* __restrict__ L, int n4)
{
    int i = blockIdx.x * blockDim.x + threadIdx.x;
    if (i >= n4) return;
    float4 v = ((const float4*)x)[i];
    __nv_bfloat16 h0 = __float2bfloat16(v.x);
    __nv_bfloat16 h1 = __float2bfloat16(v.y);
    __nv_bfloat16 h2 = __float2bfloat16(v.z);
    __nv_bfloat16 h3 = __float2bfloat16(v.w);
    __nv_bfloat16 l0 = __float2bfloat16(v.x - __bfloat162float(h0));
    __nv_bfloat16 l1 = __float2bfloat16(v.y - __bfloat162float(h1));
    __nv_bfloat16 l2 = __float2bfloat16(v.z - __bfloat162float(h2));
    __nv_bfloat16 l3 = __float2bfloat16(v.w - __bfloat162float(h3));
    ((__nv_bfloat162*)H)[2 * i + 0] = __halves2bfloat162(h0, h1);
    ((__nv_bfloat162*)H)[2 * i + 1] = __halves2bfloat162(h2, h3);
    ((__nv_bfloat162*)L)[2 * i + 0] = __halves2bfloat162(l0, l1);
    ((__nv_bfloat162*)L)[2 * i + 1] = __halves2bfloat162(l2, l3);
}

// W [K,N] -> Wt hi/lo [N,K]
__global__ void transpose_split_kernel(const float* __restrict__ W,
                                       __nv_bfloat16* __restrict__ H,
                                       __nv_bfloat16* __restrict__ L,
                                       int K, int N)
{
    __shared__ float t[32][33];
    int n = blockIdx.x * 32 + threadIdx.x;
#pragma unroll
    for (int i = 0; i < 4; i++) {
        int k = blockIdx.y * 32 + threadIdx.y + i * 8;
        t[threadIdx.y + i * 8][threadIdx.x] = W[(size_t)k * N + n];
    }
    __syncthreads();
    int k = blockIdx.y * 32 + threadIdx.x;
#pragma unroll
    for (int i = 0; i < 4; i++) {
        int nn = blockIdx.x * 32 + threadIdx.y + i * 8;
        float v = t[threadIdx.x][threadIdx.y + i * 8];
        __nv_bfloat16 h = __float2bfloat16(v);
        H[(size_t)nn * K + k] = h;
        L[(size_t)nn * K + k] = __float2bfloat16(v - __bfloat162float(h));
    }
}

// ---------------------------------------------------------------------------
// HMMA split-bf16 GEMM: C[M,N] = A[M,K] @ Bt[N,K]^T + bias
// CTA 128x128, 8 warps (warp tile 32x64), K-chunks of 64, 3-stage cp.async.
// smem per stage: Ah|Al|Bh|Bl, each 128 rows x 128B, SW128-swizzled.
// ---------------------------------------------------------------------------
#define TILE_B   16384               // one 128x128B subtile
#define STG_SZ   65536               // 4 subtiles per stage
#define NSTAGE   3

__global__ __launch_bounds__(256, 1)
void gemm_mma_kernel(const __nv_bfloat16* __restrict__ Ah,
                     const __nv_bfloat16* __restrict__ Al,
                     const __nv_bfloat16* __restrict__ Bh,   // [N,K]
                     const __nv_bfloat16* __restrict__ Bl,
                     const float* __restrict__ bias,
                     float* __restrict__ C,
                     int M, int N, int K)
{
    extern __shared__ char smem[];
    const uint32_t su = smem_u32_of(smem);
    const int tid  = threadIdx.x;
    const int wid  = tid >> 5;
    const int lane = tid & 31;
    const int m0 = blockIdx.y * 128;
    const int n0 = blockIdx.x * 128;
    const int wm = (wid & 3) * 32;     // warp m offset in tile
    const int wn = (wid >> 2) * 64;    // warp n offset in tile

    const int NC = K >> 6;             // chunks of 64

    auto load_chunk = [&](int st, int kc) {
        uint32_t sb = su + (uint32_t)st * STG_SZ;
        const int koff = kc * 64;
#pragma unroll
        for (int i = 0; i < 16; i++) {
            int f   = tid + (i << 8);          // 0..4095
            int sub = f >> 10;                 // 0:Ah 1:Al 2:Bh 3:Bl
            int r   = (f >> 3) & 127;
            int s   = f & 7;
            const __nv_bfloat16* src =
                (sub == 0) ? Ah + (size_t)(m0 + r) * K + koff + s * 8 :
                (sub == 1) ? Al + (size_t)(m0 + r) * K + koff + s * 8 :
                (sub == 2) ? Bh + (size_t)(n0 + r) * K + koff + s * 8 :
                             Bl + (size_t)(n0 + r) * K + koff + s * 8;
            uint32_t dst = sb + (uint32_t)sub * TILE_B
                         + SWZ((uint32_t)(r * 128 + s * 16));
            CP_ASYNC16(dst, src);
        }
    };

    float acc[2][8][4];
#pragma unroll
    for (int mt = 0; mt < 2; mt++)
#pragma unroll
        for (int nt = 0; nt < 8; nt++)
#pragma unroll
            for (int j = 0; j < 4; j++) acc[mt][nt][j] = 0.f;

    load_chunk(0, 0); CP_COMMIT();
    load_chunk(1, 1); CP_COMMIT();

    // ldmatrix lane address components (within-tile row, 16B col)
    const int a_row = (lane & 15);            // + wm + mt*16
    const int a_kb  = (lane & 16) ? 16 : 0;   // + ks*32
    const int b_row = (lane & 7) + ((lane & 16) ? 8 : 0);  // + wn + npair*16
    const int b_kb  = (lane & 8) ? 16 : 0;

    for (int c = 0; c < NC; c++) {
        if (c + 2 < NC) load_chunk((c + 2) % NSTAGE, c + 2);
        CP_COMMIT();
        CP_WAIT2();
        __syncthreads();

        uint32_t sb = su + (uint32_t)(c % NSTAGE) * STG_SZ;
#pragma unroll
        for (int ks = 0; ks < 4; ks++) {
            const int kb = ks * 32;
            uint32_t aH[2][4], aL[2][4], bH[8][2], bL[8][2];
#pragma unroll
            for (int mt = 0; mt < 2; mt++) {
                uint32_t off = SWZ((uint32_t)((wm + mt * 16 + a_row) * 128
                                              + kb + a_kb));
                ldsm_x4(aH[mt], sb + off);
                ldsm_x4(aL[mt], sb + TILE_B + off);
            }
#pragma unroll
            for (int np = 0; np < 4; np++) {
                uint32_t off = SWZ((uint32_t)((wn + np * 16 + b_row) * 128
                                              + kb + b_kb));
                uint32_t r[4];
                ldsm_x4(r, sb + 2 * TILE_B + off);
                bH[np * 2][0] = r[0]; bH[np * 2][1] = r[1];
                bH[np * 2 + 1][0] = r[2]; bH[np * 2 + 1][1] = r[3];
                ldsm_x4(r, sb + 3 * TILE_B + off);
                bL[np * 2][0] = r[0]; bL[np * 2][1] = r[1];
                bL[np * 2 + 1][0] = r[2]; bL[np * 2 + 1][1] = r[3];
            }
            // term-major order: long reuse distance on each accumulator
#pragma unroll
            for (int mt = 0; mt < 2; mt++)
#pragma unroll
                for (int nt = 0; nt < 8; nt++)
                    mma_bf16(acc[mt][nt], aH[mt], bH[nt]);
#pragma unroll
            for (int mt = 0; mt < 2; mt++)
#pragma unroll
                for (int nt = 0; nt < 8; nt++)
                    mma_bf16(acc[mt][nt], aH[mt], bL[nt]);
#pragma unroll
            for (int mt = 0; mt < 2; mt++)
#pragma unroll
                for (int nt = 0; nt < 8; nt++)
                    mma_bf16(acc[mt][nt], aL[mt], bH[nt]);
        }
        __syncthreads();
    }

    // Epilogue: bias + store (per mma C layout: lane l -> row l/4, col 2*(l%4))
    const int er = lane >> 2;
    const int ec = (lane & 3) * 2;
#pragma unroll
    for (int mt = 0; mt < 2; mt++) {
#pragma unroll
        for (int nt = 0; nt < 8; nt++) {
            int row = m0 + wm + mt * 16 + er;
            int col = n0 + wn + nt * 8 + ec;
            float b0 = __ldg(&bias[col]);
            float b1 = __ldg(&bias[col + 1]);
            float2 v0 = make_float2(acc[mt][nt][0] + b0, acc[mt][nt][1] + b1);
            float2 v1 = make_float2(acc[mt][nt][2] + b0, acc[mt][nt][3] + b1);
            *(float2*)(C + (size_t)row * N + col) = v0;
            *(float2*)(C + (size_t)(row + 8) * N + col) = v1;
        }
    }
}

// ---------------------------------------------------------------------------
// Causal flash attention, fp32 (unchanged; passed at rel_err 1.5e-6)
// ---------------------------------------------------------------------------
#define QP 68
#define VP 132
#define BIG_NEG (-1e30f)

__global__ __launch_bounds__(256, 1)
void flash_attn_kernel()
{
    extern __shared__ float sm[];
    float* Qs = sm;
    float* Ks = Qs + 128 * QP;
    float* Vs = Ks + 128 * QP;
    float* Ps = Vs + 64 * VP;

    const int tid = threadIdx.x;
    const int tr  = tid >> 4;
    const int tc  = tid & 15;

    const int qt   = (SEQ / 64 - 1) - blockIdx.x;
    const int bh   = blockIdx.y;
    const int b    = bh >> 4;
    const int head = bh & 15;
    const int q0   = qt * 64;

    const float* base = g_qkv + (size_t)b * SEQ * KQKV + head * HDIM;

#pragma unroll
    for (int i = 0; i < 8; i++) {
        int f  = tid + i * 256;
        int r  = f >> 5;
        int d4 = (f & 31) << 2;
        float4 v = *(const float4*)(base + (size_t)(q0 + r) * KQKV + d4);
        Qs[(d4 + 0) * QP + r] = v.x;
        Qs[(d4 + 1) * QP + r] = v.y;
        Qs[(d4 + 2) * QP + r] = v.z;
        Qs[(d4 + 3) * QP + r] = v.w;
    }

    float o[4][8];
#pragma unroll
    for (int i = 0; i < 4; i++)
#pragma unroll
        for (int j = 0; j < 8; j++) o[i][j] = 0.f;
    float mrow[4] = {BIG_NEG, BIG_NEG, BIG_NEG, BIG_NEG};
    float lrow[4] = {0.f, 0.f, 0.f, 0.f};

    const float scale = 0.088388347648318447f;

    for (int kt = 0; kt <= qt; kt++) {
        const int j0 = kt * 64;
        __syncthreads();

#pragma unroll
        for (int i = 0; i < 8; i++) {
            int f  = tid + i * 256;
            int c  = f >> 5;
            int d4 = (f & 31) << 2;
            const float* kr = base + (size_t)(j0 + c) * KQKV + HSZ + d4;
            float4 kv = *(const float4*)kr;
            Ks[(d4 + 0) * QP + c] = kv.x;
            Ks[(d4 + 1) * QP + c] = kv.y;
            Ks[(d4 + 2) * QP + c] = kv.z;
            Ks[(d4 + 3) * QP + c] = kv.w;
            *(float4*)&Vs[c * VP + d4] = *(const float4*)(kr + HSZ);
        }
        __syncthreads();

        float s[4][4];
#pragma unroll
        for (int i = 0; i < 4; i++)
#pragma unroll
            for (int j = 0; j < 4; j++) s[i][j] = 0.f;

#pragma unroll 8
        for (int k = 0; k < 128; k++) {
            float a[4], c[4];
            *(float4*)a = *(const float4*)&Qs[k * QP + tr * 4];
            *(float4*)c = *(const float4*)&Ks[k * QP + tc * 4];
#pragma unroll
            for (int i = 0; i < 4; i++)
#pragma unroll
                for (int j = 0; j < 4; j++)
                    s[i][j] += a[i] * c[j];
        }

#pragma unroll
        for (int i = 0; i < 4; i++)
#pragma unroll
            for (int j = 0; j < 4; j++) s[i][j] *= scale;

        if (kt == qt) {
#pragma unroll
            for (int i = 0; i < 4; i++)
#pragma unroll
                for (int j = 0; j < 4; j++)
                    if (tc * 4 + j > tr * 4 + i) s[i][j] = BIG_NEG;
        }

#pragma unroll
        for (int i = 0; i < 4; i++) {
            float tm = fmaxf(fmaxf(s[i][0], s[i][1]), fmaxf(s[i][2], s[i][3]));
            tm = fmaxf(tm, __shfl_xor_sync(0xffffffffu, tm, 1));
            tm = fmaxf(tm, __shfl_xor_sync(0xffffffffu, tm, 2));
            tm = fmaxf(tm, __shfl_xor_sync(0xffffffffu, tm, 4));
            tm = fmaxf(tm, __shfl_xor_sync(0xffffffffu, tm, 8));
            float mn = fmaxf(mrow[i], tm);

            float p[4];
            float rs = 0.f;
#pragma unroll
            for (int j = 0; j < 4; j++) {
                p[j] = __expf(s[i][j] - mn);
                rs += p[j];
            }
            rs += __shfl_xor_sync(0xffffffffu, rs, 1);
            rs += __shfl_xor_sync(0xffffffffu, rs, 2);
            rs += __shfl_xor_sync(0xffffffffu, rs, 4);
            rs += __shfl_xor_sync(0xffffffffu, rs, 8);

            float corr = __expf(mrow[i] - mn);
            lrow[i] = lrow[i] * corr + rs;
            mrow[i] = mn;
#pragma unroll
            for (int n = 0; n < 8; n++) o[i][n] *= corr;

            *(float4*)&Ps[(tr * 4 + i) * QP + tc * 4] =
                make_float4(p[0], p[1], p[2], p[3]);
        }
        __syncthreads();

#pragma unroll 2
        for (int j = 0; j < 64; j += 4) {
            float pa[4][4];
#pragma unroll
            for (int i = 0; i < 4; i++)
                *(float4*)pa[i] = *(const float4*)&Ps[(tr * 4 + i) * QP + j];
#pragma unroll
            for (int jj = 0; jj < 4; jj++) {
                float4 v0 = *(const float4*)&Vs[(j + jj) * VP + tc * 8];
                float4 v1 = *(const float4*)&Vs[(j + jj) * VP + tc * 8 + 4];
#pragma unroll
                for (int i = 0; i < 4; i++) {
                    o[i][0] += pa[i][jj] * v0.x;
                    o[i][1] += pa[i][jj] * v0.y;
                    o[i][2] += pa[i][jj] * v0.z;
                    o[i][3] += pa[i][jj] * v0.w;
                    o[i][4] += pa[i][jj] * v1.x;
                    o[i][5] += pa[i][jj] * v1.y;
                    o[i][6] += pa[i][jj] * v1.z;
                    o[i][7] += pa[i][jj] * v1.w;
                }
            }
        }
    }

    float* cbase = g_ctx + (size_t)(b * SEQ + q0) * HSZ + head * HDIM;
#pragma unroll
    for (int i = 0; i < 4; i++) {
        float inv = 1.f / lrow[i];
        float* dst = cbase + (size_t)(tr * 4 + i) * HSZ + tc * 8;
        float4 w0, w1;
        w0.x = o[i][0] * inv; w0.y = o[i][1] * inv;
        w0.z = o[i][2] * inv; w0.w = o[i][3] * inv;
        w1.x = o[i][4] * inv; w1.y = o[i][5] * inv;
        w1.z = o[i][6] * inv; w1.w = o[i][7] * inv;
        *(float4*)(dst)     = w0;
        *(float4*)(dst + 4) = w1;
    }
}

// ---------------------------------------------------------------------------
extern "C" void kernel_launch(void* const* d_in, const int* in_sizes, int n_in,
                              void* d_out, int out_size)
{
    const float* hs   = (const float*)d_in[0];
    // d_in[1] = ltor_mask (causal; hardcoded)
    const float* Wqkv = (const float*)d_in[2];
    const float* bqkv = (const float*)d_in[3];
    const float* Wout = (const float*)d_in[4];
    const float* bout = (const float*)d_in[5];
    float* out = (float*)d_out;

    float *qkv, *ctx;
    __nv_bfloat16 *a_hi, *a_lo, *c_hi, *c_lo, *wq_hi, *wq_lo, *wo_hi, *wo_lo;
    cudaGetSymbolAddress((void**)&qkv,   g_qkv);
    cudaGetSymbolAddress((void**)&ctx,   g_ctx);
    cudaGetSymbolAddress((void**)&a_hi,  g_a_hi);
    cudaGetSymbolAddress((void**)&a_lo,  g_a_lo);
    cudaGetSymbolAddress((void**)&c_hi,  g_c_hi);
    cudaGetSymbolAddress((void**)&c_lo,  g_c_lo);
    cudaGetSymbolAddress((void**)&wq_hi, g_wq_hi);
    cudaGetSymbolAddress((void**)&wq_lo, g_wq_lo);
    cudaGetSymbolAddress((void**)&wo_hi, g_wo_hi);
    cudaGetSymbolAddress((void**)&wo_lo, g_wo_lo);

    // Prep: split activations, transpose+split weights
    {
        int n4 = NTOK * HSZ / 4;
        split_kernel<<<n4 / 256, 256>>>(hs, a_hi, a_lo, n4);
    }
    transpose_split_kernel<<<dim3(KQKV / 32, HSZ / 32), dim3(32, 8)>>>(
        Wqkv, wq_hi, wq_lo, HSZ, KQKV);
    transpose_split_kernel<<<dim3(HSZ / 32, HSZ / 32), dim3(32, 8)>>>(
        Wout, wo_hi, wo_lo, HSZ, HSZ);

    // Tensor-core GEMMs (HMMA mma.sync, 3-term split bf16)
    const int gsm = NSTAGE * STG_SZ;   // 196608
    cudaFuncSetAttribute(gemm_mma_kernel,
                         cudaFuncAttributeMaxDynamicSharedMemorySize, gsm);

    // 1) QKV projection
    gemm_mma_kernel<<<dim3(KQKV / 128, NTOK / 128), 256, gsm>>>(
        a_hi, a_lo, wq_hi, wq_lo, bqkv, qkv, NTOK, KQKV, HSZ);

    // 2) Causal flash attention -> g_ctx
    size_t smem = (size_t)(2 * 128 * QP + 64 * VP + 64 * QP) * sizeof(float);
    cudaFuncSetAttribute(flash_attn_kernel,
                         cudaFuncAttributeMaxDynamicSharedMemorySize, (int)smem);
    flash_attn_kernel<<<dim3(SEQ / 64, NBATCH * NHEADS), 256, smem>>>();

    // 3) split ctx, output projection
    {
        int n4 = NTOK * HSZ / 4;
        split_kernel<<<n4 / 256, 256>>>(ctx, c_hi, c_lo, n4);
    }
    gemm_mma_kernel<<<dim3(HSZ / 128, NTOK / 128), 256, gsm>>>(
        c_hi, c_lo, wo_hi, wo_lo, bout, out, NTOK, HSZ, HSZ);
}

// round 6
// speedup vs baseline: 3.2588x; 1.8174x over previous
#include <cuda_runtime.h>
#include <cuda_bf16.h>
#include <math.h>
#include <stdint.h>

// Problem constants
#define HSZ    2048
#define SEQ    2048
#define NBATCH 2
#define NHEADS 16
#define HDIM   128
#define NTOK   (NBATCH * SEQ)     // 4096 tokens
#define KQKV   (3 * HSZ)          // 6144
#define QSCALE 0.08838834764831845f   // 1/sqrt(128), folded into q

// ---------------------------------------------------------------------------
// Scratch (device globals; no allocation allowed)
// ---------------------------------------------------------------------------
__device__ __nv_bfloat16 g_a_hi[(size_t)NTOK * HSZ];    // hs split
__device__ __nv_bfloat16 g_a_lo[(size_t)NTOK * HSZ];
__device__ __nv_bfloat16 g_c_hi[(size_t)NTOK * HSZ];    // ctx split (attn out)
__device__ __nv_bfloat16 g_c_lo[(size_t)NTOK * HSZ];
__device__ __nv_bfloat16 g_wq_hi[(size_t)KQKV * HSZ];   // Wqkv^T [6144,2048]
__device__ __nv_bfloat16 g_wq_lo[(size_t)KQKV * HSZ];
__device__ __nv_bfloat16 g_wo_hi[(size_t)HSZ * HSZ];    // Wout^T [2048,2048]
__device__ __nv_bfloat16 g_wo_lo[(size_t)HSZ * HSZ];
// q/k/v split, layout [bh=32][seq=2048][128] bf16 (q pre-scaled by QSCALE)
__device__ __nv_bfloat16 g_q_hi[(size_t)NTOK * HSZ];
__device__ __nv_bfloat16 g_q_lo[(size_t)NTOK * HSZ];
__device__ __nv_bfloat16 g_k_hi[(size_t)NTOK * HSZ];
__device__ __nv_bfloat16 g_k_lo[(size_t)NTOK * HSZ];
__device__ __nv_bfloat16 g_v_hi[(size_t)NTOK * HSZ];
__device__ __nv_bfloat16 g_v_lo[(size_t)NTOK * HSZ];

// ---------------------------------------------------------------------------
// Helpers
// ---------------------------------------------------------------------------
__device__ __forceinline__ uint32_t smem_u32_of(const void* p) {
    uint32_t a;
    asm("{ .reg .u64 t; cvta.to.shared.u64 t, %1; cvt.u32.u64 %0, t; }"
        : "=r"(a) : "l"(p));
    return a;
}

#define CP_ASYNC16(dst, src) \
    asm volatile("cp.async.cg.shared.global [%0], [%1], 16;" \
                 :: "r"(dst), "l"(src) : "memory")
#define CP_COMMIT()  asm volatile("cp.async.commit_group;" ::: "memory")
#define CP_WAIT2()   asm volatile("cp.async.wait_group 2;" ::: "memory")
#define CP_WAIT1()   asm volatile("cp.async.wait_group 1;" ::: "memory")
#define CP_WAIT0()   asm volatile("cp.async.wait_group 0;" ::: "memory")

#define SWZ(o) ((o) ^ (((o) >> 3) & 0x70))

__device__ __forceinline__ void ldsm_x4(uint32_t* r, uint32_t addr) {
    asm volatile("ldmatrix.sync.aligned.m8n8.x4.shared.b16 {%0,%1,%2,%3}, [%4];"
                 : "=r"(r[0]), "=r"(r[1]), "=r"(r[2]), "=r"(r[3]) : "r"(addr));
}
__device__ __forceinline__ void ldsm_x4_t(uint32_t* r, uint32_t addr) {
    asm volatile("ldmatrix.sync.aligned.m8n8.x4.trans.shared.b16 {%0,%1,%2,%3}, [%4];"
                 : "=r"(r[0]), "=r"(r[1]), "=r"(r[2]), "=r"(r[3]) : "r"(addr));
}

__device__ __forceinline__ void mma_bf16(float* c, const uint32_t* a,
                                         const uint32_t* b) {
    asm volatile(
        "mma.sync.aligned.m16n8k16.row.col.f32.bf16.bf16.f32 "
        "{%0,%1,%2,%3}, {%4,%5,%6,%7}, {%8,%9}, {%0,%1,%2,%3};"
        : "+f"(c[0]), "+f"(c[1]), "+f"(c[2]), "+f"(c[3])
        : "r"(a[0]), "r"(a[1]), "r"(a[2]), "r"(a[3]), "r"(b[0]), "r"(b[1]));
}

// split one float pair into bf16 hi/lo packed regs
__device__ __forceinline__ void split_pack(float x, float y,
                                           uint32_t& hi, uint32_t& lo) {
    __nv_bfloat16 hx = __float2bfloat16(x), hy = __float2bfloat16(y);
    __nv_bfloat162 h2 = __halves2bfloat162(hx, hy);
    hi = *reinterpret_cast<uint32_t*>(&h2);
    __nv_bfloat162 l2 = __floats2bfloat162_rn(x - __bfloat162float(hx),
                                              y - __bfloat162float(hy));
    lo = *reinterpret_cast<uint32_t*>(&l2);
}

__device__ __forceinline__ void split2_store(__nv_bfloat16* H, __nv_bfloat16* L,
                                             float v0, float v1) {
    __nv_bfloat16 h0 = __float2bfloat16(v0), h1 = __float2bfloat16(v1);
    __nv_bfloat16 l0 = __float2bfloat16(v0 - __bfloat162float(h0));
    __nv_bfloat16 l1 = __float2bfloat16(v1 - __bfloat162float(h1));
    *(__nv_bfloat162*)H = __halves2bfloat162(h0, h1);
    *(__nv_bfloat162*)L = __halves2bfloat162(l0, l1);
}

// ---------------------------------------------------------------------------
// Prep kernels
// ---------------------------------------------------------------------------
__global__ void split_kernel(const float* __restrict__ x,
                             __nv_bfloat16* __restrict__ H,
                             __nv_bfloat16* __restrict__ L, int n4)
{
    int i = blockIdx.x * blockDim.x + threadIdx.x;
    if (i >= n4) return;
    float4 v = ((const float4*)x)[i];
    __nv_bfloat16 h0 = __float2bfloat16(v.x);
    __nv_bfloat16 h1 = __float2bfloat16(v.y);
    __nv_bfloat16 h2 = __float2bfloat16(v.z);
    __nv_bfloat16 h3 = __float2bfloat16(v.w);
    __nv_bfloat16 l0 = __float2bfloat16(v.x - __bfloat162float(h0));
    __nv_bfloat16 l1 = __float2bfloat16(v.y - __bfloat162float(h1));
    __nv_bfloat16 l2 = __float2bfloat16(v.z - __bfloat162float(h2));
    __nv_bfloat16 l3 = __float2bfloat16(v.w - __bfloat162float(h3));
    ((__nv_bfloat162*)H)[2 * i + 0] = __halves2bfloat162(h0, h1);
    ((__nv_bfloat162*)H)[2 * i + 1] = __halves2bfloat162(h2, h3);
    ((__nv_bfloat162*)L)[2 * i + 0] = __halves2bfloat162(l0, l1);
    ((__nv_bfloat162*)L)[2 * i + 1] = __halves2bfloat162(l2, l3);
}

__global__ void transpose_split_kernel(const float* __restrict__ W,
                                       __nv_bfloat16* __restrict__ H,
                                       __nv_bfloat16* __restrict__ L,
                                       int K, int N)
{
    __shared__ float t[32][33];
    int n = blockIdx.x * 32 + threadIdx.x;
#pragma unroll
    for (int i = 0; i < 4; i++) {
        int k = blockIdx.y * 32 + threadIdx.y + i * 8;
        t[threadIdx.y + i * 8][threadIdx.x] = W[(size_t)k * N + n];
    }
    __syncthreads();
    int k = blockIdx.y * 32 + threadIdx.x;
#pragma unroll
    for (int i = 0; i < 4; i++) {
        int nn = blockIdx.x * 32 + threadIdx.y + i * 8;
        float v = t[threadIdx.x][threadIdx.y + i * 8];
        __nv_bfloat16 h = __float2bfloat16(v);
        H[(size_t)nn * K + k] = h;
        L[(size_t)nn * K + k] = __float2bfloat16(v - __bfloat162float(h));
    }
}

// ---------------------------------------------------------------------------
// HMMA split-bf16 GEMM (mainloop unchanged from R5; templated epilogue)
// QKV=true:  write split q/k/v buffers (q pre-scaled), per-head layout
// QKV=false: write fp32 C + bias
// ---------------------------------------------------------------------------
#define TILE_B   16384
#define STG_SZ   65536
#define NSTAGE   3

template <bool QKV>
__global__ __launch_bounds__(256, 1)
void gemm_mma_kernel(const __nv_bfloat16* __restrict__ Ah,
                     const __nv_bfloat16* __restrict__ Al,
                     const __nv_bfloat16* __restrict__ Bh,   // [N,K]
                     const __nv_bfloat16* __restrict__ Bl,
                     const float* __restrict__ bias,
                     float* __restrict__ C,
                     int M, int N, int K)
{
    extern __shared__ char smem[];
    const uint32_t su = smem_u32_of(smem);
    const int tid  = threadIdx.x;
    const int wid  = tid >> 5;
    const int lane = tid & 31;
    const int m0 = blockIdx.y * 128;
    const int n0 = blockIdx.x * 128;
    const int wm = (wid & 3) * 32;
    const int wn = (wid >> 2) * 64;

    const int NC = K >> 6;

    auto load_chunk = [&](int st, int kc) {
        uint32_t sb = su + (uint32_t)st * STG_SZ;
        const int koff = kc * 64;
#pragma unroll
        for (int i = 0; i < 16; i++) {
            int f   = tid + (i << 8);
            int sub = f >> 10;
            int r   = (f >> 3) & 127;
            int s   = f & 7;
            const __nv_bfloat16* src =
                (sub == 0) ? Ah + (size_t)(m0 + r) * K + koff + s * 8 :
                (sub == 1) ? Al + (size_t)(m0 + r) * K + koff + s * 8 :
                (sub == 2) ? Bh + (size_t)(n0 + r) * K + koff + s * 8 :
                             Bl + (size_t)(n0 + r) * K + koff + s * 8;
            uint32_t dst = sb + (uint32_t)sub * TILE_B
                         + SWZ((uint32_t)(r * 128 + s * 16));
            CP_ASYNC16(dst, src);
        }
    };

    float acc[2][8][4];
#pragma unroll
    for (int mt = 0; mt < 2; mt++)
#pragma unroll
        for (int nt = 0; nt < 8; nt++)
#pragma unroll
            for (int j = 0; j < 4; j++) acc[mt][nt][j] = 0.f;

    load_chunk(0, 0); CP_COMMIT();
    load_chunk(1, 1); CP_COMMIT();

    const int a_row = (lane & 15);
    const int a_kb  = (lane & 16) ? 16 : 0;
    const int b_row = (lane & 7) + ((lane & 16) ? 8 : 0);
    const int b_kb  = (lane & 8) ? 16 : 0;

    for (int c = 0; c < NC; c++) {
        if (c + 2 < NC) load_chunk((c + 2) % NSTAGE, c + 2);
        CP_COMMIT();
        CP_WAIT2();
        __syncthreads();

        uint32_t sb = su + (uint32_t)(c % NSTAGE) * STG_SZ;
#pragma unroll
        for (int ks = 0; ks < 4; ks++) {
            const int kb = ks * 32;
            uint32_t aH[2][4], aL[2][4], bH[8][2], bL[8][2];
#pragma unroll
            for (int mt = 0; mt < 2; mt++) {
                uint32_t off = SWZ((uint32_t)((wm + mt * 16 + a_row) * 128
                                              + kb + a_kb));
                ldsm_x4(aH[mt], sb + off);
                ldsm_x4(aL[mt], sb + TILE_B + off);
            }
#pragma unroll
            for (int np = 0; np < 4; np++) {
                uint32_t off = SWZ((uint32_t)((wn + np * 16 + b_row) * 128
                                              + kb + b_kb));
                uint32_t r[4];
                ldsm_x4(r, sb + 2 * TILE_B + off);
                bH[np * 2][0] = r[0]; bH[np * 2][1] = r[1];
                bH[np * 2 + 1][0] = r[2]; bH[np * 2 + 1][1] = r[3];
                ldsm_x4(r, sb + 3 * TILE_B + off);
                bL[np * 2][0] = r[0]; bL[np * 2][1] = r[1];
                bL[np * 2 + 1][0] = r[2]; bL[np * 2 + 1][1] = r[3];
            }
#pragma unroll
            for (int mt = 0; mt < 2; mt++)
#pragma unroll
                for (int nt = 0; nt < 8; nt++)
                    mma_bf16(acc[mt][nt], aH[mt], bH[nt]);
#pragma unroll
            for (int mt = 0; mt < 2; mt++)
#pragma unroll
                for (int nt = 0; nt < 8; nt++)
                    mma_bf16(acc[mt][nt], aH[mt], bL[nt]);
#pragma unroll
            for (int mt = 0; mt < 2; mt++)
#pragma unroll
                for (int nt = 0; nt < 8; nt++)
                    mma_bf16(acc[mt][nt], aL[mt], bH[nt]);
        }
        __syncthreads();
    }

    const int er = lane >> 2;
    const int ec = (lane & 3) * 2;

    if (QKV) {
        const int part = n0 >> 11;                  // 0=q 1=k 2=v
        const int head = (n0 & 2047) >> 7;
        __nv_bfloat16* DH = (part == 0) ? g_q_hi : (part == 1) ? g_k_hi : g_v_hi;
        __nv_bfloat16* DL = (part == 0) ? g_q_lo : (part == 1) ? g_k_lo : g_v_lo;
        const float qs = (part == 0) ? QSCALE : 1.0f;
#pragma unroll
        for (int mt = 0; mt < 2; mt++) {
#pragma unroll
            for (int nt = 0; nt < 8; nt++) {
                int token = m0 + wm + mt * 16 + er;
                int d = wn + nt * 8 + ec;
                float b0 = __ldg(&bias[n0 + d]);
                float b1 = __ldg(&bias[n0 + d + 1]);
                int bb = token >> 11, s = token & 2047;
                size_t base = ((size_t)(bb * 16 + head) * SEQ + s) * 128 + d;
                split2_store(DH + base, DL + base,
                             (acc[mt][nt][0] + b0) * qs,
                             (acc[mt][nt][1] + b1) * qs);
                size_t base2 = base + (size_t)8 * 128;   // token+8
                split2_store(DH + base2, DL + base2,
                             (acc[mt][nt][2] + b0) * qs,
                             (acc[mt][nt][3] + b1) * qs);
            }
        }
    } else {
#pragma unroll
        for (int mt = 0; mt < 2; mt++) {
#pragma unroll
            for (int nt = 0; nt < 8; nt++) {
                int row = m0 + wm + mt * 16 + er;
                int col = n0 + wn + nt * 8 + ec;
                float b0 = __ldg(&bias[col]);
                float b1 = __ldg(&bias[col + 1]);
                float2 v0 = make_float2(acc[mt][nt][0] + b0, acc[mt][nt][1] + b1);
                float2 v1 = make_float2(acc[mt][nt][2] + b0, acc[mt][nt][3] + b1);
                *(float2*)(C + (size_t)row * N + col) = v0;
                *(float2*)(C + (size_t)(row + 8) * N + col) = v1;
            }
        }
    }
}

// ---------------------------------------------------------------------------
// HMMA flash attention. CTA: 128 q-rows x one (b,head). 8 warps x 16 rows.
// K-tiles of 64 keys, double-buffered cp.async. 3-term split bf16 for both
// S = Q K^T (q pre-scaled) and O += P V. Writes ctx as split bf16.
// smem: Qh[2][128][128B] | Ql | 2 stages of (Kh|Kl|Vh|Vl, each [2][64][128B])
// ---------------------------------------------------------------------------
#define FA_QB   32768u     // one Q buffer (hi or lo)
#define FA_KVB  16384u     // one K or V buffer per stage
#define FA_STG  65536u     // stage = Kh|Kl|Vh|Vl
#define FA_SMEM (2u * FA_QB + 2u * FA_STG)   // 196608

__global__ __launch_bounds__(256, 1)
void flash_mma_kernel()
{
    extern __shared__ char smem[];
    const uint32_t su = smem_u32_of(smem);
    const int tid  = threadIdx.x;
    const int w    = tid >> 5;
    const int lane = tid & 31;

    const int qt   = 15 - blockIdx.x;           // heavy tiles first
    const int bh   = blockIdx.y;
    const int head = bh & 15;
    const int q0   = qt * 128;
    const int ntile = 2 * qt + 2;

    // ---- Q tile load (both hi/lo), group 0 together with KV tile 0 ----
#pragma unroll
    for (int i = 0; i < 16; i++) {
        int f   = tid + (i << 8);
        int buf = f >> 11;            // 0 hi, 1 lo
        int r   = (f >> 4) & 127;
        int cs  = f & 15;
        const __nv_bfloat16* src = (buf ? g_q_lo : g_q_hi)
            + ((size_t)bh * SEQ + q0 + r) * 128 + cs * 8;
        uint32_t dst = su + (uint32_t)buf * FA_QB + (uint32_t)(cs >> 3) * 16384u
                     + SWZ((uint32_t)(r * 128 + (cs & 7) * 16));
        CP_ASYNC16(dst, src);
    }

    auto load_kv = [&](int st, int t) {
        const int j0 = t * 64;
        uint32_t sb = su + 2u * FA_QB + (uint32_t)st * FA_STG;
#pragma unroll
        for (int i = 0; i < 16; i++) {
            int f   = tid + (i << 8);
            int buf = f >> 10;        // 0 kh, 1 kl, 2 vh, 3 vl
            int r   = (f >> 4) & 63;
            int cs  = f & 15;
            const __nv_bfloat16* base =
                (buf == 0) ? g_k_hi : (buf == 1) ? g_k_lo :
                (buf == 2) ? g_v_hi : g_v_lo;
            const __nv_bfloat16* src = base
                + ((size_t)bh * SEQ + j0 + r) * 128 + cs * 8;
            uint32_t dst = sb + (uint32_t)buf * FA_KVB
                         + (uint32_t)(cs >> 3) * 8192u
                         + SWZ((uint32_t)(r * 128 + (cs & 7) * 16));
            CP_ASYNC16(dst, src);
        }
    };

    load_kv(0, 0);
    CP_COMMIT();

    float oacc[16][4];
#pragma unroll
    for (int i = 0; i < 16; i++)
#pragma unroll
        for (int j = 0; j < 4; j++) oacc[i][j] = 0.f;
    float mrow0 = -1e30f, mrow1 = -1e30f;
    float lrow0 = 0.f, lrow1 = 0.f;

    const int a_row = lane & 15;
    const int a_kb  = (lane & 16) ? 16 : 0;
    const int b_row = (lane & 7) + ((lane & 16) ? 8 : 0);
    const int b_kb  = (lane & 8) ? 16 : 0;
    const int v_row = lane & 15;
    const int v_cb  = (lane & 16) ? 16 : 0;

    for (int t = 0; t < ntile; t++) {
        if (t + 1 < ntile) { load_kv((t + 1) & 1, t + 1); CP_COMMIT(); }
        if (t + 1 < ntile) { CP_WAIT1(); } else { CP_WAIT0(); }
        __syncthreads();

        const uint32_t sb = su + 2u * FA_QB + (uint32_t)(t & 1) * FA_STG;
        const int j0 = t * 64;
        const bool active = (j0 < q0 + w * 16 + 16);

        if (active) {
            // ---- S = Q K^T (3-term split) ----
            float sacc[8][4];
#pragma unroll
            for (int nt = 0; nt < 8; nt++)
#pragma unroll
                for (int j = 0; j < 4; j++) sacc[nt][j] = 0.f;

#pragma unroll
            for (int ks = 0; ks < 8; ks++) {
                const int chunk = ks >> 2;
                const int kb = (ks & 3) * 32;
                uint32_t aoff = (uint32_t)(chunk * 16384)
                    + SWZ((uint32_t)((w * 16 + a_row) * 128 + kb + a_kb));
                uint32_t aH[4], aL[4];
                ldsm_x4(aH, su + aoff);
                ldsm_x4(aL, su + FA_QB + aoff);
                uint32_t bH[8][2], bL[8][2];
#pragma unroll
                for (int np = 0; np < 4; np++) {
                    uint32_t boff = (uint32_t)(chunk * 8192)
                        + SWZ((uint32_t)((np * 16 + b_row) * 128 + kb + b_kb));
                    uint32_t r4[4];
                    ldsm_x4(r4, sb + boff);
                    bH[np * 2][0] = r4[0]; bH[np * 2][1] = r4[1];
                    bH[np * 2 + 1][0] = r4[2]; bH[np * 2 + 1][1] = r4[3];
                    ldsm_x4(r4, sb + FA_KVB + boff);
                    bL[np * 2][0] = r4[0]; bL[np * 2][1] = r4[1];
                    bL[np * 2 + 1][0] = r4[2]; bL[np * 2 + 1][1] = r4[3];
                }
#pragma unroll
                for (int nt = 0; nt < 8; nt++) mma_bf16(sacc[nt], aH, bH[nt]);
#pragma unroll
                for (int nt = 0; nt < 8; nt++) mma_bf16(sacc[nt], aH, bL[nt]);
#pragma unroll
                for (int nt = 0; nt < 8; nt++) mma_bf16(sacc[nt], aL, bH[nt]);
            }

            // ---- causal mask (only near diagonal) ----
            if (j0 + 63 > q0 + w * 16) {
                const int rg = q0 + w * 16 + (lane >> 2);
#pragma unroll
                for (int nt = 0; nt < 8; nt++) {
                    int cbase = j0 + nt * 8 + 2 * (lane & 3);
                    if (cbase > rg)     sacc[nt][0] = -1e30f;
                    if (cbase + 1 > rg) sacc[nt][1] = -1e30f;
                    if (cbase > rg + 8)     sacc[nt][2] = -1e30f;
                    if (cbase + 1 > rg + 8) sacc[nt][3] = -1e30f;
                }
            }

            // ---- online softmax (rows spread over quad lanes) ----
            float t0 = -1e30f, t1 = -1e30f;
#pragma unroll
            for (int nt = 0; nt < 8; nt++) {
                t0 = fmaxf(t0, fmaxf(sacc[nt][0], sacc[nt][1]));
                t1 = fmaxf(t1, fmaxf(sacc[nt][2], sacc[nt][3]));
            }
            t0 = fmaxf(t0, __shfl_xor_sync(0xffffffffu, t0, 1));
            t0 = fmaxf(t0, __shfl_xor_sync(0xffffffffu, t0, 2));
            t1 = fmaxf(t1, __shfl_xor_sync(0xffffffffu, t1, 1));
            t1 = fmaxf(t1, __shfl_xor_sync(0xffffffffu, t1, 2));
            float mn0 = fmaxf(mrow0, t0), mn1 = fmaxf(mrow1, t1);
            float corr0 = __expf(mrow0 - mn0), corr1 = __expf(mrow1 - mn1);

            float rs0 = 0.f, rs1 = 0.f;
#pragma unroll
            for (int nt = 0; nt < 8; nt++) {
                sacc[nt][0] = __expf(sacc[nt][0] - mn0);
                sacc[nt][1] = __expf(sacc[nt][1] - mn0);
                sacc[nt][2] = __expf(sacc[nt][2] - mn1);
                sacc[nt][3] = __expf(sacc[nt][3] - mn1);
                rs0 += sacc[nt][0] + sacc[nt][1];
                rs1 += sacc[nt][2] + sacc[nt][3];
            }
            rs0 += __shfl_xor_sync(0xffffffffu, rs0, 1);
            rs0 += __shfl_xor_sync(0xffffffffu, rs0, 2);
            rs1 += __shfl_xor_sync(0xffffffffu, rs1, 1);
            rs1 += __shfl_xor_sync(0xffffffffu, rs1, 2);
            lrow0 = lrow0 * corr0 + rs0;
            lrow1 = lrow1 * corr1 + rs1;
            mrow0 = mn0; mrow1 = mn1;
#pragma unroll
            for (int nd = 0; nd < 16; nd++) {
                oacc[nd][0] *= corr0; oacc[nd][1] *= corr0;
                oacc[nd][2] *= corr1; oacc[nd][3] *= corr1;
            }

            // ---- O += P V (3-term split; P frags direct from sacc) ----
#pragma unroll
            for (int t4 = 0; t4 < 4; t4++) {
                uint32_t aPh[4], aPl[4];
                split_pack(sacc[2 * t4][0],     sacc[2 * t4][1],     aPh[0], aPl[0]);
                split_pack(sacc[2 * t4][2],     sacc[2 * t4][3],     aPh[1], aPl[1]);
                split_pack(sacc[2 * t4 + 1][0], sacc[2 * t4 + 1][1], aPh[2], aPl[2]);
                split_pack(sacc[2 * t4 + 1][2], sacc[2 * t4 + 1][3], aPh[3], aPl[3]);
#pragma unroll
                for (int g = 0; g < 8; g++) {
                    uint32_t voff = (uint32_t)((g >> 2) * 8192)
                        + SWZ((uint32_t)((t4 * 16 + v_row) * 128
                                         + ((32 * g) & 127) + v_cb));
                    uint32_t vh[4], vl[4];
                    ldsm_x4_t(vh, sb + 2u * FA_KVB + voff);
                    ldsm_x4_t(vl, sb + 3u * FA_KVB + voff);
                    mma_bf16(oacc[2 * g],     aPh, vh);
                    mma_bf16(oacc[2 * g + 1], aPh, vh + 2);
                    mma_bf16(oacc[2 * g],     aPh, vl);
                    mma_bf16(oacc[2 * g + 1], aPh, vl + 2);
                    mma_bf16(oacc[2 * g],     aPl, vh);
                    mma_bf16(oacc[2 * g + 1], aPl, vh + 2);
                }
            }
        }
        __syncthreads();
    }

    // ---- epilogue: normalize, write ctx split bf16 ----
    const float inv0 = 1.f / lrow0;
    const float inv1 = 1.f / lrow1;
    const int srow = q0 + w * 16 + (lane >> 2);
    const int token = (bh >> 4) * SEQ + srow;
    const size_t base = (size_t)token * HSZ + head * 128;
#pragma unroll
    for (int nd = 0; nd < 16; nd++) {
        const int d = nd * 8 + 2 * (lane & 3);
        split2_store(g_c_hi + base + d, g_c_lo + base + d,
                     oacc[nd][0] * inv0, oacc[nd][1] * inv0);
        split2_store(g_c_hi + base + (size_t)8 * HSZ + d,
                     g_c_lo + base + (size_t)8 * HSZ + d,
                     oacc[nd][2] * inv1, oacc[nd][3] * inv1);
    }
}

// ---------------------------------------------------------------------------
extern "C" void kernel_launch(void* const* d_in, const int* in_sizes, int n_in,
                              void* d_out, int out_size)
{
    const float* hs   = (const float*)d_in[0];
    // d_in[1] = ltor_mask (causal; hardcoded)
    const float* Wqkv = (const float*)d_in[2];
    const float* bqkv = (const float*)d_in[3];
    const float* Wout = (const float*)d_in[4];
    const float* bout = (const float*)d_in[5];
    float* out = (float*)d_out;

    __nv_bfloat16 *a_hi, *a_lo, *c_hi, *c_lo, *wq_hi, *wq_lo, *wo_hi, *wo_lo;
    cudaGetSymbolAddress((void**)&a_hi,  g_a_hi);
    cudaGetSymbolAddress((void**)&a_lo,  g_a_lo);
    cudaGetSymbolAddress((void**)&c_hi,  g_c_hi);
    cudaGetSymbolAddress((void**)&c_lo,  g_c_lo);
    cudaGetSymbolAddress((void**)&wq_hi, g_wq_hi);
    cudaGetSymbolAddress((void**)&wq_lo, g_wq_lo);
    cudaGetSymbolAddress((void**)&wo_hi, g_wo_hi);
    cudaGetSymbolAddress((void**)&wo_lo, g_wo_lo);

    // Prep
    {
        int n4 = NTOK * HSZ / 4;
        split_kernel<<<n4 / 256, 256>>>(hs, a_hi, a_lo, n4);
    }
    transpose_split_kernel<<<dim3(KQKV / 32, HSZ / 32), dim3(32, 8)>>>(
        Wqkv, wq_hi, wq_lo, HSZ, KQKV);
    transpose_split_kernel<<<dim3(HSZ / 32, HSZ / 32), dim3(32, 8)>>>(
        Wout, wo_hi, wo_lo, HSZ, HSZ);

    const int gsm = NSTAGE * STG_SZ;   // 196608
    cudaFuncSetAttribute(gemm_mma_kernel<true>,
                         cudaFuncAttributeMaxDynamicSharedMemorySize, gsm);
    cudaFuncSetAttribute(gemm_mma_kernel<false>,
                         cudaFuncAttributeMaxDynamicSharedMemorySize, gsm);
    cudaFuncSetAttribute(flash_mma_kernel,
                         cudaFuncAttributeMaxDynamicSharedMemorySize,
                         (int)FA_SMEM);

    // 1) QKV projection -> split q/k/v (q pre-scaled)
    gemm_mma_kernel<true><<<dim3(KQKV / 128, NTOK / 128), 256, gsm>>>(
        a_hi, a_lo, wq_hi, wq_lo, bqkv, nullptr, NTOK, KQKV, HSZ);

    // 2) HMMA causal flash attention -> split ctx
    flash_mma_kernel<<<dim3(SEQ / 128, NBATCH * NHEADS), 256, FA_SMEM>>>();

    // 3) Output projection -> d_out fp32
    gemm_mma_kernel<false><<<dim3(HSZ / 128, NTOK / 128), 256, gsm>>>(
        c_hi, c_lo, wo_hi, wo_lo, bout, out, NTOK, HSZ, HSZ);
}